// round 15
// baseline (speedup 1.0000x reference)
#include <cuda_runtime.h>
#include <cuda_bf16.h>

// PhyGate R14 (= R13 resubmit; prior bench died on device-acquisition infra
// error, kernel never ran): champion memory shape (2 rows/thread, float2,
// 256-thr flat) + packed f32x2 SIMD math. The two rows per thread are
// independent and symmetric, so FMA-class ops are packed via fma.rn.f32x2 /
// mul.rn.f32x2 (FFMA2 — PTX-only per SASS_QUICKREF), halving FMA-pipe issue.
// MUFU (exp/rcp/rsqrt/sqrt) and clamps stay scalar per row.

typedef unsigned long long u64;

__device__ __forceinline__ float fast_rcp(float x) {
    float y; asm("rcp.approx.f32 %0, %1;" : "=f"(y) : "f"(x)); return y;
}
__device__ __forceinline__ float fast_sqrt(float x) {
    float y; asm("sqrt.approx.f32 %0, %1;" : "=f"(y) : "f"(x)); return y;
}
__device__ __forceinline__ u64 pk(float lo, float hi) {
    u64 r; asm("mov.b64 %0, {%1, %2};" : "=l"(r) : "f"(lo), "f"(hi)); return r;
}
__device__ __forceinline__ void upk(u64 p, float& lo, float& hi) {
    asm("mov.b64 {%0, %1}, %2;" : "=f"(lo), "=f"(hi) : "l"(p));
}
__device__ __forceinline__ u64 fma2(u64 a, u64 b, u64 c) {
    u64 d; asm("fma.rn.f32x2 %0, %1, %2, %3;" : "=l"(d) : "l"(a), "l"(b), "l"(c)); return d;
}
__device__ __forceinline__ u64 mul2(u64 a, u64 b) {
    u64 d; asm("mul.rn.f32x2 %0, %1, %2;" : "=l"(d) : "l"(a), "l"(b)); return d;
}
__device__ __forceinline__ u64 neg2(u64 a) {           // flip both sign bits
    return a ^ 0x8000000080000000ULL;                  // LOP3, alu pipe
}

__global__ void __launch_bounds__(256)
phygate_kernel(const float* __restrict__ b,
               const float* __restrict__ v,
               const float* __restrict__ w,
               const float* __restrict__ dt,
               const float* __restrict__ lin_w,
               const float* __restrict__ lin_b,
               const float* __restrict__ p1,
               const float* __restrict__ p2,
               const float* __restrict__ p3,
               const float* __restrict__ p4,
               const float* __restrict__ p5,
               const float* __restrict__ p6,
               float* __restrict__ out, int n)
{
    // Scalar uniforms.
    float s_dt   = __ldg(dt);
    float s_lw   = __ldg(lin_w);
    float s_lb   = __ldg(lin_b);
    float s_p1   = __ldg(p1);
    float s_p2   = __ldg(p2);
    float s_p3x  = __ldg(p3 + 0);
    float s_p3y  = __ldg(p3 + 1);
    float s_p3zg = __ldg(p3 + 2) - 9.81f;
    float s_p5   = __ldg(p5);
    float s_r    = __ldg(p6);
    float s_k45  = __ldg(p4) * (1.0f + s_p5);
    float s_c15r = 1.5f / s_r;

    // Packed (broadcast) uniforms for the f32x2 datapath.
    u64 r2    = pk(s_r, s_r);
    u64 negr2 = neg2(r2);
    u64 p22   = pk(s_p2, s_p2);
    u64 p3x2  = pk(s_p3x, s_p3x);
    u64 p3y2  = pk(s_p3y, s_p3y);
    u64 p3z2  = pk(s_p3zg, s_p3zg);
    u64 dt2   = pk(s_dt, s_dt);

    int n2 = n >> 1;
    int t = blockIdx.x * blockDim.x + threadIdx.x;

    if (t < n2) {
        float2 b2 = reinterpret_cast<const float2*>(b)[t];
        const float2* v2p = reinterpret_cast<const float2*>(v) + 3 * t;
        const float2* w2p = reinterpret_cast<const float2*>(w) + 3 * t;
        float2 va = v2p[0], vb = v2p[1], vc = v2p[2];
        float2 wa = w2p[0], wb = w2p[1], wc = w2p[2];

        // Pack components: (row0, row1) per lane.
        u64 vx2 = pk(va.x, vb.y), vy2 = pk(va.y, vc.x), vz2 = pk(vb.x, vc.y);
        u64 wx2 = pk(wa.x, wb.y), wy2 = pk(wa.y, wc.x), wz2 = pk(wb.x, wc.y);

        // Gates (scalar: MUFU-bound anyway).
        float z0 = fmaf(b2.x, s_lw, s_lb);
        float z1 = fmaf(b2.y, s_lw, s_lb);
        float g0 = fast_rcp(1.0f + __expf(-z0));
        float g1 = fast_rcp(1.0f + __expf(-z1));
        u64 gate1_2 = pk(g0, g1);
        u64 gate2_2 = pk(1.0f - g0, 1.0f - g1);

        // al (packed up to the norm, scalar through rsqrt/clamp).
        u64 t1_2 = fma2(wy2, negr2, vx2);               // vx - r*wy
        u64 t2_2 = fma2(wx2, r2, vy2);                  // vy + r*wx
        u64 s2   = fma2(t1_2, t1_2, mul2(t2_2, t2_2));
        float s0, s1, vz0, vz1;
        upk(s2, s0, s1);
        upk(vz2, vz0, vz1);
        float al0 = fminf(s_k45 * fabsf(vz0) * rsqrtf(s0 + 1e-6f), 0.4f);
        float al1 = fminf(s_k45 * fabsf(vz1) * rsqrtf(s1 + 1e-6f), 0.4f);
        u64 al2   = pk(al0, al1);
        u64 oma2  = pk(1.0f - al0, 1.0f - al1);
        u64 om15_2 = pk(fmaf(-1.5f, al0, 1.0f), fmaf(-1.5f, al1, 1.0f));
        u64 c2    = pk(al0 * s_c15r, al1 * s_c15r);
        u64 vbz2  = pk(-s_p5 * vz0, -s_p5 * vz1);

        u64 alr2 = mul2(al2, r2);
        u64 vbx2 = fma2(oma2, vx2, mul2(alr2, wy2));
        u64 vby2 = fma2(oma2, vy2, neg2(mul2(alr2, wx2)));
        u64 wbx2 = fma2(neg2(c2), vy2, mul2(om15_2, wx2));
        u64 wby2 = fma2(c2, vx2, mul2(om15_2, wy2));

        u64 v2x2 = fma2(gate1_2, vx2, mul2(gate2_2, vbx2));
        u64 v2y2 = fma2(gate1_2, vy2, mul2(gate2_2, vby2));
        u64 v2z2 = fma2(gate1_2, vz2, mul2(gate2_2, vbz2));
        u64 w2x2 = fma2(gate1_2, wx2, mul2(gate2_2, wbx2));
        u64 w2y2 = fma2(gate1_2, wy2, mul2(gate2_2, wby2));
        u64 w2z2 = fma2(gate1_2, wz2, mul2(gate2_2, wz2));

        // Norm (scalar sqrt), k = -p1*nv.
        u64 ns2 = fma2(v2x2, v2x2, fma2(v2y2, v2y2, mul2(v2z2, v2z2)));
        float ns0, ns1;
        upk(ns2, ns0, ns1);
        u64 k2 = pk(-s_p1 * fast_sqrt(ns0), -s_p1 * fast_sqrt(ns1));

        // cross(w2, v2), packed.
        u64 cx2 = fma2(w2y2, v2z2, neg2(mul2(w2z2, v2y2)));
        u64 cy2 = fma2(w2z2, v2x2, neg2(mul2(w2x2, v2z2)));
        u64 cz2 = fma2(w2x2, v2y2, neg2(mul2(w2y2, v2x2)));

        u64 ax2 = fma2(k2, v2x2, fma2(p22, cx2, p3x2));
        u64 ay2 = fma2(k2, v2y2, fma2(p22, cy2, p3y2));
        u64 az2 = fma2(k2, v2z2, fma2(p22, cz2, p3z2));

        u64 ovx2 = fma2(ax2, dt2, v2x2);
        u64 ovy2 = fma2(ay2, dt2, v2y2);
        u64 ovz2 = fma2(az2, dt2, v2z2);

        // Unpack and store (same layout as champion).
        float ov0x, ov1x, ov0y, ov1y, ov0z, ov1z;
        float ow0x, ow1x, ow0y, ow1y, ow0z, ow1z;
        upk(ovx2, ov0x, ov1x); upk(ovy2, ov0y, ov1y); upk(ovz2, ov0z, ov1z);
        upk(w2x2, ow0x, ow1x); upk(w2y2, ow0y, ow1y); upk(w2z2, ow0z, ow1z);

        float2* outv = reinterpret_cast<float2*>(out) + 3 * t;
        float2* outw = reinterpret_cast<float2*>(out + 3 * (size_t)n) + 3 * t;
        outv[0] = make_float2(ov0x, ov0y);
        outv[1] = make_float2(ov0z, ov1x);
        outv[2] = make_float2(ov1y, ov1z);
        outw[0] = make_float2(ow0x, ow0y);
        outw[1] = make_float2(ow0z, ow1x);
        outw[2] = make_float2(ow1y, ow1z);
    }

    // Tail row if n is odd (scalar path).
    if ((n & 1) && t == 0) {
        int row = n - 1;
        float bb = b[row];
        float vx = v[3*row], vy = v[3*row+1], vz = v[3*row+2];
        float wx = w[3*row], wy = w[3*row+1], wz = w[3*row+2];

        float z = fmaf(bb, s_lw, s_lb);
        float g1v = fast_rcp(1.0f + __expf(-z));
        float g2v = 1.0f - g1v;
        float t1 = vx - wy * s_r, t2 = vy + wx * s_r;
        float al = fminf(s_k45 * fabsf(vz) * rsqrtf(fmaf(t1,t1,fmaf(t2,t2,1e-6f))), 0.4f);
        float oma = 1.0f - al;
        float vbx = fmaf(oma, vx, al * s_r * wy);
        float vby = fmaf(oma, vy, -(al * s_r) * wx);
        float vbz = -s_p5 * vz;
        float c = al * s_c15r;
        float om15 = fmaf(-1.5f, al, 1.0f);
        float wbx = fmaf(-c, vy, om15 * wx);
        float wby = fmaf(c, vx, om15 * wy);
        float v2x = fmaf(g1v, vx, g2v * vbx);
        float v2y = fmaf(g1v, vy, g2v * vby);
        float v2z = fmaf(g1v, vz, g2v * vbz);
        float w2x = fmaf(g1v, wx, g2v * wbx);
        float w2y = fmaf(g1v, wy, g2v * wby);
        float w2z = fmaf(g1v, wz, g2v * wz);
        float nv = fast_sqrt(fmaf(v2x,v2x,fmaf(v2y,v2y,v2z*v2z)));
        float k = -s_p1 * nv;
        float cx = w2y*v2z - w2z*v2y, cy = w2z*v2x - w2x*v2z, cz = w2x*v2y - w2y*v2x;
        float ax = fmaf(k, v2x, fmaf(s_p2, cx, s_p3x));
        float ay = fmaf(k, v2y, fmaf(s_p2, cy, s_p3y));
        float az = fmaf(k, v2z, fmaf(s_p2, cz, s_p3zg));
        out[3*row]   = fmaf(ax, s_dt, v2x);
        out[3*row+1] = fmaf(ay, s_dt, v2y);
        out[3*row+2] = fmaf(az, s_dt, v2z);
        float* ow_base = out + 3 * (size_t)n;
        ow_base[3*row] = w2x; ow_base[3*row+1] = w2y; ow_base[3*row+2] = w2z;
    }
}

extern "C" void kernel_launch(void* const* d_in, const int* in_sizes, int n_in,
                              void* d_out, int out_size)
{
    const float* b     = (const float*)d_in[0];
    const float* v     = (const float*)d_in[1];
    const float* w     = (const float*)d_in[2];
    const float* dt    = (const float*)d_in[3];
    const float* lin_w = (const float*)d_in[4];
    const float* lin_b = (const float*)d_in[5];
    const float* p1    = (const float*)d_in[6];
    const float* p2    = (const float*)d_in[7];
    const float* p3    = (const float*)d_in[8];
    const float* p4    = (const float*)d_in[9];
    const float* p5    = (const float*)d_in[10];
    const float* p6    = (const float*)d_in[11];

    int n = in_sizes[0];  // B rows
    int n2 = (n + 1) >> 1;
    int threads = 256;
    int blocks = (n2 + threads - 1) / threads;

    phygate_kernel<<<blocks, threads>>>(b, v, w, dt, lin_w, lin_b,
                                        p1, p2, p3, p4, p5, p6,
                                        (float*)d_out, n);
}

// round 16
// speedup vs baseline: 1.0987x; 1.0987x over previous
#include <cuda_runtime.h>
#include <cuda_bf16.h>

// PhyGate R15: champion (2 rows/thread, float2, scalar fast-math, 40 regs)
// with 128-thread blocks — finer scheduling granularity, smaller tails.
// Final knob; everything else is falsified. Structural floor: ~16.2us ncu
// (48MB compulsory write-drain + L2 read service).

struct Params {
    float dt, lin_w, lin_b;
    float p1, p2;
    float p3x, p3y, p3zg;   // p3z - 9.81 pre-folded
    float p5, p6;
    float k45;              // p4 * (1 + p5)
    float c15_over_r;       // 1.5 / r
};

__device__ __forceinline__ float fast_rcp(float x) {
    float y; asm("rcp.approx.f32 %0, %1;" : "=f"(y) : "f"(x)); return y;
}
__device__ __forceinline__ float fast_sqrt(float x) {
    float y; asm("sqrt.approx.f32 %0, %1;" : "=f"(y) : "f"(x)); return y;
}

__device__ __forceinline__ void phygate_row(
    float bb, float vx, float vy, float vz, float wx, float wy, float wz,
    const Params& P,
    float& ovx, float& ovy, float& ovz, float& owx, float& owy, float& owz)
{
    float z = fmaf(bb, P.lin_w, P.lin_b);
    float gate1 = fast_rcp(1.0f + __expf(-z));
    float gate2 = 1.0f - gate1;

    float r = P.p6;
    float t1 = vx - wy * r;
    float t2 = vy + wx * r;
    float inv = rsqrtf(fmaf(t1, t1, fmaf(t2, t2, 1e-6f)));
    float al = P.k45 * fabsf(vz) * inv;
    al = fminf(al, 0.4f);
    float oma = 1.0f - al;

    float vbx = fmaf(oma, vx, al * r * wy);
    float vby = fmaf(oma, vy, -(al * r) * wx);
    float vbz = -P.p5 * vz;

    float c = al * P.c15_over_r;
    float om15 = fmaf(-1.5f, al, 1.0f);
    float wbx = fmaf(-c, vy, om15 * wx);
    float wby = fmaf(c, vx, om15 * wy);
    float wbz = wz;

    float v2x = fmaf(gate1, vx, gate2 * vbx);
    float v2y = fmaf(gate1, vy, gate2 * vby);
    float v2z = fmaf(gate1, vz, gate2 * vbz);
    float w2x = fmaf(gate1, wx, gate2 * wbx);
    float w2y = fmaf(gate1, wy, gate2 * wby);
    float w2z = fmaf(gate1, wz, gate2 * wbz);

    float nv = fast_sqrt(fmaf(v2x, v2x, fmaf(v2y, v2y, v2z * v2z)));

    float cx = w2y * v2z - w2z * v2y;
    float cy = w2z * v2x - w2x * v2z;
    float cz = w2x * v2y - w2y * v2x;

    float k = -P.p1 * nv;
    float ax = fmaf(k, v2x, fmaf(P.p2, cx, P.p3x));
    float ay = fmaf(k, v2y, fmaf(P.p2, cy, P.p3y));
    float az = fmaf(k, v2z, fmaf(P.p2, cz, P.p3zg));

    ovx = fmaf(ax, P.dt, v2x);
    ovy = fmaf(ay, P.dt, v2y);
    ovz = fmaf(az, P.dt, v2z);
    owx = w2x; owy = w2y; owz = w2z;
}

__global__ void __launch_bounds__(128)
phygate_kernel(const float* __restrict__ b,
               const float* __restrict__ v,
               const float* __restrict__ w,
               const float* __restrict__ dt,
               const float* __restrict__ lin_w,
               const float* __restrict__ lin_b,
               const float* __restrict__ p1,
               const float* __restrict__ p2,
               const float* __restrict__ p3,
               const float* __restrict__ p4,
               const float* __restrict__ p5,
               const float* __restrict__ p6,
               float* __restrict__ out, int n)
{
    Params P;
    P.dt = __ldg(dt); P.lin_w = __ldg(lin_w); P.lin_b = __ldg(lin_b);
    P.p1 = __ldg(p1); P.p2 = __ldg(p2);
    P.p3x = __ldg(p3 + 0); P.p3y = __ldg(p3 + 1); P.p3zg = __ldg(p3 + 2) - 9.81f;
    float p4v = __ldg(p4);
    P.p5 = __ldg(p5); P.p6 = __ldg(p6);
    P.k45 = p4v * (1.0f + P.p5);
    P.c15_over_r = 1.5f / P.p6;

    int n2 = n >> 1;
    int t = blockIdx.x * blockDim.x + threadIdx.x;

    if (t < n2) {
        float2 b2 = reinterpret_cast<const float2*>(b)[t];
        const float2* v2p = reinterpret_cast<const float2*>(v) + 3 * t;
        const float2* w2p = reinterpret_cast<const float2*>(w) + 3 * t;
        float2 va = v2p[0], vb = v2p[1], vc = v2p[2];
        float2 wa = w2p[0], wb = w2p[1], wc = w2p[2];

        float ov0x, ov0y, ov0z, ow0x, ow0y, ow0z;
        float ov1x, ov1y, ov1z, ow1x, ow1y, ow1z;

        phygate_row(b2.x, va.x, va.y, vb.x, wa.x, wa.y, wb.x, P,
                    ov0x, ov0y, ov0z, ow0x, ow0y, ow0z);
        phygate_row(b2.y, vb.y, vc.x, vc.y, wb.y, wc.x, wc.y, P,
                    ov1x, ov1y, ov1z, ow1x, ow1y, ow1z);

        float2* outv = reinterpret_cast<float2*>(out) + 3 * t;
        float2* outw = reinterpret_cast<float2*>(out + 3 * (size_t)n) + 3 * t;
        outv[0] = make_float2(ov0x, ov0y);
        outv[1] = make_float2(ov0z, ov1x);
        outv[2] = make_float2(ov1y, ov1z);
        outw[0] = make_float2(ow0x, ow0y);
        outw[1] = make_float2(ow0z, ow1x);
        outw[2] = make_float2(ow1y, ow1z);
    }

    // Tail row if n is odd.
    if ((n & 1) && t == 0) {
        int row = n - 1;
        float ovx, ovy, ovz, owx, owy, owz;
        phygate_row(b[row], v[3*row], v[3*row+1], v[3*row+2],
                    w[3*row], w[3*row+1], w[3*row+2], P,
                    ovx, ovy, ovz, owx, owy, owz);
        out[3*row] = ovx; out[3*row+1] = ovy; out[3*row+2] = ovz;
        float* ow_base = out + 3 * (size_t)n;
        ow_base[3*row] = owx; ow_base[3*row+1] = owy; ow_base[3*row+2] = owz;
    }
}

extern "C" void kernel_launch(void* const* d_in, const int* in_sizes, int n_in,
                              void* d_out, int out_size)
{
    const float* b     = (const float*)d_in[0];
    const float* v     = (const float*)d_in[1];
    const float* w     = (const float*)d_in[2];
    const float* dt    = (const float*)d_in[3];
    const float* lin_w = (const float*)d_in[4];
    const float* lin_b = (const float*)d_in[5];
    const float* p1    = (const float*)d_in[6];
    const float* p2    = (const float*)d_in[7];
    const float* p3    = (const float*)d_in[8];
    const float* p4    = (const float*)d_in[9];
    const float* p5    = (const float*)d_in[10];
    const float* p6    = (const float*)d_in[11];

    int n = in_sizes[0];  // B rows
    int n2 = (n + 1) >> 1;
    int threads = 128;
    int blocks = (n2 + threads - 1) / threads;

    phygate_kernel<<<blocks, threads>>>(b, v, w, dt, lin_w, lin_b,
                                        p1, p2, p3, p4, p5, p6,
                                        (float*)d_out, n);
}